// round 1
// baseline (speedup 1.0000x reference)
#include <cuda_runtime.h>
#include <cuda_bf16.h>
#include <mma.h>

using namespace nvcuda;
typedef __nv_bfloat16 bf16;

// ---------------- problem constants ----------------
#define NB    8
#define SQ    1024
#define SKV   1024
#define EDIM  1024
#define VOC   32000
#define NL    6
#define MTOT  (NB * SQ)        // 8192
#define SCALE_Q 0.125f         // (E/H)^-0.5 = 64^-0.5

// ---------------- device scratch (allocation-free rule: __device__ globals) ----------------
__device__ bf16  g_x_h [MTOT * EDIM];
__device__ bf16  g_x_l [MTOT * EDIM];
__device__ bf16  g_T_h [MTOT * EDIM];
__device__ bf16  g_T_l [MTOT * EDIM];
__device__ bf16  g_q_h [MTOT * EDIM];
__device__ bf16  g_q_l [MTOT * EDIM];
__device__ bf16  g_k_h [MTOT * EDIM];
__device__ bf16  g_k_l [MTOT * EDIM];
__device__ bf16  g_vT_h[MTOT * EDIM];
__device__ bf16  g_vT_l[MTOT * EDIM];
__device__ bf16  g_p_h [NB * SQ * SKV];
__device__ bf16  g_p_l [NB * SQ * SKV];
__device__ bf16  g_o_h [MTOT * EDIM];
__device__ bf16  g_o_l [MTOT * EDIM];
__device__ float g_scores[NB * SQ * SKV];
__device__ bf16  g_w_h [3 * EDIM * EDIM];
__device__ bf16  g_w_l [3 * EDIM * EDIM];
__device__ bf16  g_wo_h[EDIM * EDIM];
__device__ bf16  g_wo_l[EDIM * EDIM];
__device__ bf16  g_lin_h[VOC * EDIM];
__device__ bf16  g_lin_l[VOC * EDIM];

// ---------------- helpers ----------------
__device__ __forceinline__ void split2(float v, bf16& h, bf16& l) {
    h = __float2bfloat16(v);
    l = __float2bfloat16(v - __bfloat162float(h));
}

// fp32 -> (hi, lo) bf16 split, grid-stride
__global__ void split_arr(const float* __restrict__ src, bf16* __restrict__ h,
                          bf16* __restrict__ l, size_t n) {
    size_t stride = (size_t)gridDim.x * blockDim.x;
    for (size_t i = (size_t)blockIdx.x * blockDim.x + threadIdx.x; i < n; i += stride) {
        split2(src[i], h[i], l[i]);
    }
}

// embedding gather + split: one block per (b, s) row
__global__ void gather_split(const int* __restrict__ idx, const float* __restrict__ embed,
                             bf16* __restrict__ xh, bf16* __restrict__ xl) {
    int row = blockIdx.x;
    int tok = idx[row];
    const float* src = embed + (size_t)tok * EDIM;
    bf16* h = xh + (size_t)row * EDIM;
    bf16* l = xl + (size_t)row * EDIM;
    for (int c = threadIdx.x; c < EDIM; c += blockDim.x) {
        split2(src[c], h[c], l[c]);
    }
}

// row softmax over 1024 cols -> hi/lo bf16; one block (256 thr) per row
__global__ void softmax_split(const float* __restrict__ S, bf16* __restrict__ Ph,
                              bf16* __restrict__ Pl) {
    int row = blockIdx.x;
    int t = threadIdx.x;
    const float* s = S + (size_t)row * SKV;

    float v[4];
    float lm = -1e30f;
#pragma unroll
    for (int i = 0; i < 4; i++) { v[i] = s[t + i * 256]; lm = fmaxf(lm, v[i]); }

    __shared__ float red[256];
    red[t] = lm; __syncthreads();
#pragma unroll
    for (int off = 128; off > 0; off >>= 1) {
        if (t < off) red[t] = fmaxf(red[t], red[t + off]);
        __syncthreads();
    }
    float mx = red[0];
    __syncthreads();

    float ls = 0.f;
#pragma unroll
    for (int i = 0; i < 4; i++) { v[i] = __expf(v[i] - mx); ls += v[i]; }
    red[t] = ls; __syncthreads();
#pragma unroll
    for (int off = 128; off > 0; off >>= 1) {
        if (t < off) red[t] += red[t + off];
        __syncthreads();
    }
    float inv = 1.f / red[0];

    bf16* ph = Ph + (size_t)row * SKV;
    bf16* pl = Pl + (size_t)row * SKV;
#pragma unroll
    for (int i = 0; i < 4; i++) {
        bf16 h, l;
        split2(v[i] * inv, h, l);
        ph[t + i * 256] = h;
        pl[t + i * 256] = l;
    }
}

// ---------------- generic NT GEMM: C[m,n] = alpha * sum_k A[m,k]*B[n,k] + bias[n] ----------------
// A,B given as bf16 (hi,lo) pairs; compute Ah*Bh + Ah*Bl + Al*Bh with fp32 accumulate.
// Optional fp32 output Cf and/or split bf16 output Ch/Cl. TRANS: store at [n*ldc + m].
#define BM 128
#define BN 64
#define BK 32

template <bool TRANS>
__global__ void __launch_bounds__(256)
gemm_nt(const bf16* __restrict__ Ah, const bf16* __restrict__ Al, size_t sA,
        const bf16* __restrict__ Bh, const bf16* __restrict__ Bl, size_t sB,
        float* __restrict__ Cf, bf16* __restrict__ Ch, bf16* __restrict__ Cl, size_t sC,
        int M, int N, int K, int ldc, float alpha, const float* __restrict__ bias) {
    __shared__ __align__(32) bf16 sAh[BM * BK];
    __shared__ __align__(32) bf16 sAl[BM * BK];
    __shared__ __align__(32) bf16 sBh[BN * BK];
    __shared__ __align__(32) bf16 sBl[BN * BK];
    __shared__ __align__(32) float stage[8 * 256];

    const int z = blockIdx.z;
    Ah += (size_t)z * sA; Al += (size_t)z * sA;
    Bh += (size_t)z * sB; Bl += (size_t)z * sB;

    const int m0 = blockIdx.y * BM;
    const int n0 = blockIdx.x * BN;
    const int t = threadIdx.x;
    const int w = t >> 5, lane = t & 31;
    const int wm = w >> 1, wn = w & 1;

    wmma::fragment<wmma::accumulator, 16, 16, 16, float> c[2][2];
#pragma unroll
    for (int i = 0; i < 2; i++)
#pragma unroll
        for (int j = 0; j < 2; j++) wmma::fill_fragment(c[i][j], 0.f);

    for (int k0 = 0; k0 < K; k0 += BK) {
        // load A tile (128 x 32), hi & lo, vectorized 16B
#pragma unroll
        for (int e = t; e < (BM * BK / 8); e += 256) {
            int row = e >> 2, cc = e & 3;
            size_t goff = (size_t)(m0 + row) * K + k0 + cc * 8;
            reinterpret_cast<uint4*>(sAh)[e] = *reinterpret_cast<const uint4*>(Ah + goff);
            reinterpret_cast<uint4*>(sAl)[e] = *reinterpret_cast<const uint4*>(Al + goff);
        }
        // load B tile (64 x 32)
        {
            int e = t;  // exactly BN*BK/8 = 256 chunks
            int row = e >> 2, cc = e & 3;
            size_t goff = (size_t)(n0 + row) * K + k0 + cc * 8;
            reinterpret_cast<uint4*>(sBh)[e] = *reinterpret_cast<const uint4*>(Bh + goff);
            reinterpret_cast<uint4*>(sBl)[e] = *reinterpret_cast<const uint4*>(Bl + goff);
        }
        __syncthreads();

#pragma unroll
        for (int kk = 0; kk < BK; kk += 16) {
            wmma::fragment<wmma::matrix_a, 16, 16, 16, bf16, wmma::row_major> ah[2], al[2];
            wmma::fragment<wmma::matrix_b, 16, 16, 16, bf16, wmma::col_major> bh[2], bl[2];
#pragma unroll
            for (int i = 0; i < 2; i++) {
                wmma::load_matrix_sync(ah[i], sAh + (wm * 32 + i * 16) * BK + kk, BK);
                wmma::load_matrix_sync(al[i], sAl + (wm * 32 + i * 16) * BK + kk, BK);
            }
#pragma unroll
            for (int j = 0; j < 2; j++) {
                wmma::load_matrix_sync(bh[j], sBh + (wn * 32 + j * 16) * BK + kk, BK);
                wmma::load_matrix_sync(bl[j], sBl + (wn * 32 + j * 16) * BK + kk, BK);
            }
#pragma unroll
            for (int i = 0; i < 2; i++)
#pragma unroll
                for (int j = 0; j < 2; j++) {
                    wmma::mma_sync(c[i][j], ah[i], bh[j], c[i][j]);
                    wmma::mma_sync(c[i][j], ah[i], bl[j], c[i][j]);
                    wmma::mma_sync(c[i][j], al[i], bh[j], c[i][j]);
                }
        }
        __syncthreads();
    }

    // epilogue: stage each 16x16 frag through shared, apply alpha/bias, write out
    float* st = stage + w * 256;
#pragma unroll
    for (int i = 0; i < 2; i++)
#pragma unroll
        for (int j = 0; j < 2; j++) {
            wmma::store_matrix_sync(st, c[i][j], 16, wmma::mem_row_major);
            __syncwarp();
            int rbase = m0 + wm * 32 + i * 16;
            int cbase = n0 + wn * 32 + j * 16;
#pragma unroll
            for (int e = lane; e < 256; e += 32) {
                int r = e >> 4, col = e & 15;
                int gr = rbase + r, gc = cbase + col;
                float v = st[e] * alpha;
                if (bias) v += bias[gc];
                size_t idx;
                if (TRANS) idx = (size_t)z * sC + (size_t)gc * ldc + gr;
                else       idx = (size_t)z * sC + (size_t)gr * ldc + gc;
                if (Cf) Cf[idx] = v;
                if (Ch) {
                    bf16 h, l;
                    split2(v, h, l);
                    Ch[idx] = h;
                    Cl[idx] = l;
                }
            }
            __syncwarp();
        }
}

// ---------------- host-side launcher ----------------
static void launch_gemm(bool trans,
                        const bf16* Ah, const bf16* Al, size_t sA,
                        const bf16* Bh, const bf16* Bl, size_t sB,
                        float* Cf, bf16* Ch, bf16* Cl, size_t sC,
                        int M, int N, int K, int ldc, float alpha,
                        const float* bias, int batch) {
    dim3 grid(N / BN, M / BM, batch);
    if (trans)
        gemm_nt<true><<<grid, 256>>>(Ah, Al, sA, Bh, Bl, sB, Cf, Ch, Cl, sC,
                                     M, N, K, ldc, alpha, bias);
    else
        gemm_nt<false><<<grid, 256>>>(Ah, Al, sA, Bh, Bl, sB, Cf, Ch, Cl, sC,
                                      M, N, K, ldc, alpha, bias);
}

#define SYM(var, sym)                                   \
    do {                                                \
        void* _p = nullptr;                             \
        cudaGetSymbolAddress(&_p, sym);                 \
        var = (decltype(var))_p;                        \
    } while (0)

extern "C" void kernel_launch(void* const* d_in, const int* in_sizes, int n_in,
                              void* d_out, int out_size) {
    const int*   input_text = (const int*)d_in[0];
    const float* target     = (const float*)d_in[1];
    const float* embed      = (const float*)d_in[2];
    const float* in_proj_w  = (const float*)d_in[3];
    const float* out_w      = (const float*)d_in[4];
    const float* out_b      = (const float*)d_in[5];
    const float* lin_w      = (const float*)d_in[6];
    const float* lin_b      = (const float*)d_in[7];
    float*       logits     = (float*)d_out;

    bf16 *x_h, *x_l, *T_h, *T_l, *q_h, *q_l, *k_h, *k_l, *vT_h, *vT_l;
    bf16 *p_h, *p_l, *o_h, *o_l, *w_h, *w_l, *wo_h, *wo_l, *lin_h, *lin_l;
    float* sc;
    SYM(x_h, g_x_h);   SYM(x_l, g_x_l);
    SYM(T_h, g_T_h);   SYM(T_l, g_T_l);
    SYM(q_h, g_q_h);   SYM(q_l, g_q_l);
    SYM(k_h, g_k_h);   SYM(k_l, g_k_l);
    SYM(vT_h, g_vT_h); SYM(vT_l, g_vT_l);
    SYM(p_h, g_p_h);   SYM(p_l, g_p_l);
    SYM(o_h, g_o_h);   SYM(o_l, g_o_l);
    SYM(w_h, g_w_h);   SYM(w_l, g_w_l);
    SYM(wo_h, g_wo_h); SYM(wo_l, g_wo_l);
    SYM(lin_h, g_lin_h); SYM(lin_l, g_lin_l);
    SYM(sc, g_scores);

    // embed gather -> x (hi/lo)
    gather_split<<<MTOT, 256>>>(input_text, embed, x_h, x_l);
    // target_text split (used as K/V input every layer)
    split_arr<<<8192, 256>>>(target, T_h, T_l, (size_t)MTOT * EDIM);
    // lin_w split (for final logits GEMM)
    split_arr<<<16384, 256>>>(lin_w, lin_h, lin_l, (size_t)VOC * EDIM);

    const size_t EE = (size_t)EDIM * EDIM;

    for (int l = 0; l < NL; l++) {
        split_arr<<<8192, 256>>>(in_proj_w + (size_t)l * 3 * EE, w_h, w_l, 3 * EE);
        split_arr<<<4096, 256>>>(out_w + (size_t)l * EE, wo_h, wo_l, EE);

        // q = (x @ Wq^T) * SCALE          [8192, 1024]
        launch_gemm(false, x_h, x_l, 0, w_h, w_l, 0,
                    nullptr, q_h, q_l, 0,
                    MTOT, EDIM, EDIM, EDIM, SCALE_Q, nullptr, 1);
        // k = target @ Wk^T               [8192, 1024]
        launch_gemm(false, T_h, T_l, 0, w_h + EE, w_l + EE, 0,
                    nullptr, k_h, k_l, 0,
                    MTOT, EDIM, EDIM, EDIM, 1.f, nullptr, 1);
        // vT[b] = (target_b @ Wv^T)^T     [B][E][SKV]  (transposed store)
        launch_gemm(true, T_h, T_l, (size_t)SKV * EDIM, w_h + 2 * EE, w_l + 2 * EE, 0,
                    nullptr, vT_h, vT_l, (size_t)EDIM * SKV,
                    SKV, EDIM, EDIM, SKV, 1.f, nullptr, NB);
        // scores[b] = q_b @ k_b^T         [B][SQ][SKV], fp32
        launch_gemm(false, q_h, q_l, (size_t)SQ * EDIM, k_h, k_l, (size_t)SKV * EDIM,
                    sc, nullptr, nullptr, (size_t)SQ * SKV,
                    SQ, SKV, EDIM, SKV, 1.f, nullptr, NB);
        // attn = softmax(scores)          -> hi/lo bf16
        softmax_split<<<NB * SQ, 256>>>(sc, p_h, p_l);
        // o[b] = attn_b @ v_b = attn_b @ vT_b^T   [B][SQ][E]
        launch_gemm(false, p_h, p_l, (size_t)SQ * SKV, vT_h, vT_l, (size_t)EDIM * SKV,
                    nullptr, o_h, o_l, (size_t)SQ * EDIM,
                    SQ, EDIM, SKV, EDIM, 1.f, nullptr, NB);
        // x = o @ out_w^T + out_b         [8192, 1024]
        launch_gemm(false, o_h, o_l, 0, wo_h, wo_l, 0,
                    nullptr, x_h, x_l, 0,
                    MTOT, EDIM, EDIM, EDIM, 1.f, out_b + (size_t)l * EDIM, 1);
    }

    // logits = x @ lin_w^T + lin_b        [8192, 32000] fp32 -> d_out
    launch_gemm(false, x_h, x_l, 0, lin_h, lin_l, 0,
                logits, nullptr, nullptr, 0,
                MTOT, VOC, EDIM, VOC, 1.f, lin_b, 1);
}

// round 6
// speedup vs baseline: 1.9423x; 1.9423x over previous
#include <cuda_runtime.h>
#include <cuda_bf16.h>
#include <cstdint>

typedef __nv_bfloat16 bf16;

// ---------------- problem constants ----------------
#define NB    8
#define SQ    1024
#define SKV   1024
#define EDIM  1024
#define VOC   32000
#define NL    6
#define MTOT  (NB * SQ)        // 8192
#define SCALE_Q 0.125f

// ---------------- device scratch ----------------
__device__ bf16  g_x_h [MTOT * EDIM];
__device__ bf16  g_x_l [MTOT * EDIM];
__device__ bf16  g_T_h [MTOT * EDIM];
__device__ bf16  g_T_l [MTOT * EDIM];
__device__ bf16  g_q_h [MTOT * EDIM];
__device__ bf16  g_q_l [MTOT * EDIM];
__device__ bf16  g_k_h [MTOT * EDIM];
__device__ bf16  g_k_l [MTOT * EDIM];
__device__ bf16  g_vT_h[MTOT * EDIM];
__device__ bf16  g_vT_l[MTOT * EDIM];
__device__ bf16  g_p_h [NB * SQ * SKV];
__device__ bf16  g_p_l [NB * SQ * SKV];
__device__ bf16  g_o_h [MTOT * EDIM];
__device__ bf16  g_o_l [MTOT * EDIM];
__device__ float g_scores[NB * SQ * SKV];
__device__ bf16  g_w_h [3 * EDIM * EDIM];
__device__ bf16  g_w_l [3 * EDIM * EDIM];
__device__ bf16  g_wo_h[EDIM * EDIM];
__device__ bf16  g_wo_l[EDIM * EDIM];
__device__ bf16  g_lin_h[VOC * EDIM];
__device__ bf16  g_lin_l[VOC * EDIM];

// ---------------- elementwise helpers ----------------
__device__ __forceinline__ void split2(float v, bf16& h, bf16& l) {
    h = __float2bfloat16(v);
    l = __float2bfloat16(v - __bfloat162float(h));
}

__global__ void split_arr(const float* __restrict__ src, bf16* __restrict__ h,
                          bf16* __restrict__ l, size_t n) {
    size_t stride = (size_t)gridDim.x * blockDim.x;
    for (size_t i = (size_t)blockIdx.x * blockDim.x + threadIdx.x; i < n; i += stride)
        split2(src[i], h[i], l[i]);
}

__global__ void gather_split(const int* __restrict__ idx, const float* __restrict__ embed,
                             bf16* __restrict__ xh, bf16* __restrict__ xl) {
    int row = blockIdx.x;
    int tok = idx[row];
    const float* src = embed + (size_t)tok * EDIM;
    bf16* h = xh + (size_t)row * EDIM;
    bf16* l = xl + (size_t)row * EDIM;
    for (int c = threadIdx.x; c < EDIM; c += blockDim.x)
        split2(src[c], h[c], l[c]);
}

__global__ void softmax_split(const float* __restrict__ S, bf16* __restrict__ Ph,
                              bf16* __restrict__ Pl) {
    int row = blockIdx.x;
    int t = threadIdx.x;
    const float* s = S + (size_t)row * SKV;
    float v[4];
    float lm = -1e30f;
#pragma unroll
    for (int i = 0; i < 4; i++) { v[i] = s[t + i * 256]; lm = fmaxf(lm, v[i]); }
    __shared__ float red[256];
    red[t] = lm; __syncthreads();
#pragma unroll
    for (int off = 128; off > 0; off >>= 1) {
        if (t < off) red[t] = fmaxf(red[t], red[t + off]);
        __syncthreads();
    }
    float mx = red[0];
    __syncthreads();
    float ls = 0.f;
#pragma unroll
    for (int i = 0; i < 4; i++) { v[i] = __expf(v[i] - mx); ls += v[i]; }
    red[t] = ls; __syncthreads();
#pragma unroll
    for (int off = 128; off > 0; off >>= 1) {
        if (t < off) red[t] += red[t + off];
        __syncthreads();
    }
    float inv = 1.f / red[0];
    bf16* ph = Ph + (size_t)row * SKV;
    bf16* pl = Pl + (size_t)row * SKV;
#pragma unroll
    for (int i = 0; i < 4; i++) {
        bf16 h, l;
        split2(v[i] * inv, h, l);
        ph[t + i * 256] = h;
        pl[t + i * 256] = l;
    }
}

// ---------------- mma.sync GEMM (sm_80-baseline PTX only) ----------------
// C[m,n] = alpha * sum_k A[m,k]*B[n,k] (+ bias[n]); 3-term bf16 hi/lo split, fp32 acc.
// Tile 128x128x32, 256 threads (8 warps, 2x4), warp tile 64x32, 3-stage cp.async.

#define BK        32
#define LDROW     80                        // padded row pitch in bytes (40 bf16)
#define ASPLIT_B  (128 * LDROW)             // 10240 B per split array per stage
#define STAGE_B   (4 * ASPLIT_B)            // Ah, Al, Bh, Bl = 40960 B
#define NSTAGE    3
#define EPIL_LD   132                       // floats per staged row (16B-aligned rows)
#define GSMEM     (NSTAGE * STAGE_B)        // 122880 B (>= 128*132*4 = 67584 epilogue)

__device__ __forceinline__ uint32_t smem_u32(const void* p) {
    uint32_t a;
    asm("{ .reg .u64 t; cvta.to.shared.u64 t, %1; cvt.u32.u64 %0, t; }" : "=r"(a) : "l"(p));
    return a;
}

__device__ __forceinline__ void ldm_x4(uint32_t& r0, uint32_t& r1, uint32_t& r2,
                                       uint32_t& r3, uint32_t addr) {
    asm volatile("ldmatrix.sync.aligned.m8n8.x4.shared.b16 {%0,%1,%2,%3}, [%4];"
                 : "=r"(r0), "=r"(r1), "=r"(r2), "=r"(r3) : "r"(addr));
}

__device__ __forceinline__ void mma16816(float* c, const uint32_t* a, const uint32_t* b) {
    asm volatile(
        "mma.sync.aligned.m16n8k16.row.col.f32.bf16.bf16.f32 "
        "{%0,%1,%2,%3}, {%4,%5,%6,%7}, {%8,%9}, {%0,%1,%2,%3};"
        : "+f"(c[0]), "+f"(c[1]), "+f"(c[2]), "+f"(c[3])
        : "r"(a[0]), "r"(a[1]), "r"(a[2]), "r"(a[3]), "r"(b[0]), "r"(b[1]));
}

__device__ __forceinline__ void fill_stage(uint32_t sbase,
    const bf16* __restrict__ A0, const bf16* __restrict__ A1,
    const bf16* __restrict__ B0, const bf16* __restrict__ B1,
    int K, int k0, int tid)
{
    const bf16* gs[4] = {A0, A1, B0, B1};
#pragma unroll
    for (int a = 0; a < 4; a++) {
#pragma unroll
        for (int j = 0; j < 2; j++) {
            int e = tid + j * 256;            // 0..511: 128 rows x 4 16B chunks
            int row = e >> 2, c = e & 3;
            uint32_t dst = sbase + a * ASPLIT_B + row * LDROW + c * 16;
            uint64_t src = __cvta_generic_to_global((const void*)(gs[a] + (size_t)row * K + k0 + c * 8));
            asm volatile("cp.async.cg.shared.global [%0], [%1], 16;" :: "r"(dst), "l"(src));
        }
    }
    asm volatile("cp.async.commit_group;" ::: "memory");
}

template <bool TRANS>
__global__ void __launch_bounds__(256, 1)
gemm_mma(const bf16* __restrict__ Ah, const bf16* __restrict__ Al, size_t sA,
         const bf16* __restrict__ Bh, const bf16* __restrict__ Bl, size_t sB,
         float* __restrict__ Cf, bf16* __restrict__ Ch, bf16* __restrict__ Cl, size_t sC,
         int M, int N, int K, int ldc, float alpha, const float* __restrict__ bias)
{
    extern __shared__ __align__(128) char smem[];
    const uint32_t sb = smem_u32(smem);
    const int tid  = threadIdx.x;
    const int wid  = tid >> 5;
    const int lane = tid & 31;
    const int wm = wid >> 2;                  // 0..1 : 64-row block
    const int wn = wid & 3;                   // 0..3 : 32-col block
    const int z  = blockIdx.z;
    const int m0 = blockIdx.y * 128;
    const int n0 = blockIdx.x * 128;

    const bf16* A0 = Ah + (size_t)z * sA + (size_t)m0 * K;
    const bf16* A1 = Al + (size_t)z * sA + (size_t)m0 * K;
    const bf16* B0 = Bh + (size_t)z * sB + (size_t)n0 * K;
    const bf16* B1 = Bl + (size_t)z * sB + (size_t)n0 * K;

    // per-thread ldmatrix base offsets (bytes) within a split array
    const uint32_t a_base = (uint32_t)((wm * 64 + (lane & 15)) * LDROW + (lane >> 4) * 16);
    const uint32_t b_base = (uint32_t)((wn * 32 + (lane >> 4) * 8 + (lane & 7)) * LDROW
                                       + ((lane >> 3) & 1) * 16);

    float acc[4][4][4];
#pragma unroll
    for (int i = 0; i < 4; i++)
#pragma unroll
        for (int j = 0; j < 4; j++)
#pragma unroll
            for (int r = 0; r < 4; r++) acc[i][j][r] = 0.f;

    const int KT = K / BK;

    fill_stage(sb + 0 * STAGE_B, A0, A1, B0, B1, K, 0, tid);
    fill_stage(sb + 1 * STAGE_B, A0, A1, B0, B1, K, BK, tid);

    int stage = 0;
    for (int kt = 0; kt < KT; kt++) {
        asm volatile("cp.async.wait_group 1;" ::: "memory");
        __syncthreads();

        // prefetch (overwrites the stage read in iter kt-1; safe after the sync)
        int f = kt + 2;
        if (f < KT) {
            int fs = f % NSTAGE;
            fill_stage(sb + fs * STAGE_B, A0, A1, B0, B1, K, f * BK, tid);
        } else {
            asm volatile("cp.async.commit_group;" ::: "memory");
        }

        const uint32_t sAh = sb + stage * STAGE_B;
        const uint32_t sAl = sAh + ASPLIT_B;
        const uint32_t sBh = sAh + 2 * ASPLIT_B;
        const uint32_t sBl = sAh + 3 * ASPLIT_B;

#pragma unroll
        for (int ks = 0; ks < 2; ks++) {
            const uint32_t ko = ks * 32;      // 16 bf16 = 32 bytes
            uint32_t ah[4][4], al[4][4], bh[4][2], bl[4][2];
#pragma unroll
            for (int mi = 0; mi < 4; mi++) {
                uint32_t off = a_base + mi * 16 * LDROW + ko;
                ldm_x4(ah[mi][0], ah[mi][1], ah[mi][2], ah[mi][3], sAh + off);
                ldm_x4(al[mi][0], al[mi][1], al[mi][2], al[mi][3], sAl + off);
            }
#pragma unroll
            for (int p = 0; p < 2; p++) {     // each x4 covers two n8 blocks
                uint32_t off = b_base + p * 16 * LDROW + ko;
                ldm_x4(bh[2 * p][0], bh[2 * p][1], bh[2 * p + 1][0], bh[2 * p + 1][1], sBh + off);
                ldm_x4(bl[2 * p][0], bl[2 * p][1], bl[2 * p + 1][0], bl[2 * p + 1][1], sBl + off);
            }
#pragma unroll
            for (int mi = 0; mi < 4; mi++)
#pragma unroll
                for (int ni = 0; ni < 4; ni++) {
                    mma16816(acc[mi][ni], ah[mi], bh[ni]);
                    mma16816(acc[mi][ni], ah[mi], bl[ni]);
                    mma16816(acc[mi][ni], al[mi], bh[ni]);
                }
        }
        stage = (stage + 1 == NSTAGE) ? 0 : stage + 1;
    }

    // drain remaining cp.async groups (tail commits) before reusing smem
    asm volatile("cp.async.wait_group 0;" ::: "memory");
    __syncthreads();

    // ---------------- epilogue ----------------
    float* SE = reinterpret_cast<float*>(smem);
    const int tr = lane >> 2;                 // 0..7
    const int tc = (lane & 3) * 2;            // 0,2,4,6
#pragma unroll
    for (int mi = 0; mi < 4; mi++)
#pragma unroll
        for (int ni = 0; ni < 4; ni++) {
            int r0 = wm * 64 + mi * 16 + tr;
            int c0 = wn * 32 + ni * 8 + tc;
            if (!TRANS) {
                SE[r0 * EPIL_LD + c0]           = acc[mi][ni][0];
                SE[r0 * EPIL_LD + c0 + 1]       = acc[mi][ni][1];
                SE[(r0 + 8) * EPIL_LD + c0]     = acc[mi][ni][2];
                SE[(r0 + 8) * EPIL_LD + c0 + 1] = acc[mi][ni][3];
            } else {  // store transposed: SE[col][row]
                SE[c0 * EPIL_LD + r0]           = acc[mi][ni][0];
                SE[(c0 + 1) * EPIL_LD + r0]     = acc[mi][ni][1];
                SE[c0 * EPIL_LD + r0 + 8]       = acc[mi][ni][2];
                SE[(c0 + 1) * EPIL_LD + r0 + 8] = acc[mi][ni][3];
            }
        }
    __syncthreads();

    // coalesced write: SE is [outer 128][inner 128]; out[(OB+outer)*ldc + IB+inner]
    const int OB = TRANS ? n0 : m0;
    const int IB = TRANS ? m0 : n0;
#pragma unroll
    for (int i = 0; i < 16; i++) {
        int e = tid + i * 256;                // 0..4095
        int row = e >> 5;
        int c4 = (e & 31) * 4;
        float4 v = *reinterpret_cast<float4*>(&SE[row * EPIL_LD + c4]);
        v.x *= alpha; v.y *= alpha; v.z *= alpha; v.w *= alpha;
        if (!TRANS && bias) {
            v.x += bias[n0 + c4];
            v.y += bias[n0 + c4 + 1];
            v.z += bias[n0 + c4 + 2];
            v.w += bias[n0 + c4 + 3];
        }
        size_t o = (size_t)z * sC + (size_t)(OB + row) * ldc + IB + c4;
        if (Cf) *reinterpret_cast<float4*>(Cf + o) = v;
        if (Ch) {
            bf16 h0, l0, h1, l1, h2, l2, h3, l3;
            split2(v.x, h0, l0); split2(v.y, h1, l1);
            split2(v.z, h2, l2); split2(v.w, h3, l3);
            __nv_bfloat162 hp0 = {h0, h1}, hp1 = {h2, h3};
            __nv_bfloat162 lp0 = {l0, l1}, lp1 = {l2, l3};
            uint2 hu = make_uint2(*(uint32_t*)&hp0, *(uint32_t*)&hp1);
            uint2 lu = make_uint2(*(uint32_t*)&lp0, *(uint32_t*)&lp1);
            *reinterpret_cast<uint2*>(Ch + o) = hu;
            *reinterpret_cast<uint2*>(Cl + o) = lu;
        }
    }
}

// ---------------- host-side launcher ----------------
static void launch_gemm(bool trans,
                        const bf16* Ah, const bf16* Al, size_t sA,
                        const bf16* Bh, const bf16* Bl, size_t sB,
                        float* Cf, bf16* Ch, bf16* Cl, size_t sC,
                        int M, int N, int K, int ldc, float alpha,
                        const float* bias, int batch) {
    dim3 grid(N / 128, M / 128, batch);
    if (trans)
        gemm_mma<true><<<grid, 256, GSMEM>>>(Ah, Al, sA, Bh, Bl, sB, Cf, Ch, Cl, sC,
                                             M, N, K, ldc, alpha, bias);
    else
        gemm_mma<false><<<grid, 256, GSMEM>>>(Ah, Al, sA, Bh, Bl, sB, Cf, Ch, Cl, sC,
                                              M, N, K, ldc, alpha, bias);
}

#define SYM(var, sym)                                   \
    do {                                                \
        void* _p = nullptr;                             \
        cudaGetSymbolAddress(&_p, sym);                 \
        var = (decltype(var))_p;                        \
    } while (0)

extern "C" void kernel_launch(void* const* d_in, const int* in_sizes, int n_in,
                              void* d_out, int out_size) {
    const int*   input_text = (const int*)d_in[0];
    const float* target     = (const float*)d_in[1];
    const float* embed      = (const float*)d_in[2];
    const float* in_proj_w  = (const float*)d_in[3];
    const float* out_w      = (const float*)d_in[4];
    const float* out_b      = (const float*)d_in[5];
    const float* lin_w      = (const float*)d_in[6];
    const float* lin_b      = (const float*)d_in[7];
    float*       logits     = (float*)d_out;

    cudaFuncSetAttribute(gemm_mma<false>, cudaFuncAttributeMaxDynamicSharedMemorySize, GSMEM);
    cudaFuncSetAttribute(gemm_mma<true>,  cudaFuncAttributeMaxDynamicSharedMemorySize, GSMEM);

    bf16 *x_h, *x_l, *T_h, *T_l, *q_h, *q_l, *k_h, *k_l, *vT_h, *vT_l;
    bf16 *p_h, *p_l, *o_h, *o_l, *w_h, *w_l, *wo_h, *wo_l, *lin_h, *lin_l;
    float* sc;
    SYM(x_h, g_x_h);   SYM(x_l, g_x_l);
    SYM(T_h, g_T_h);   SYM(T_l, g_T_l);
    SYM(q_h, g_q_h);   SYM(q_l, g_q_l);
    SYM(k_h, g_k_h);   SYM(k_l, g_k_l);
    SYM(vT_h, g_vT_h); SYM(vT_l, g_vT_l);
    SYM(p_h, g_p_h);   SYM(p_l, g_p_l);
    SYM(o_h, g_o_h);   SYM(o_l, g_o_l);
    SYM(w_h, g_w_h);   SYM(w_l, g_w_l);
    SYM(wo_h, g_wo_h); SYM(wo_l, g_wo_l);
    SYM(lin_h, g_lin_h); SYM(lin_l, g_lin_l);
    SYM(sc, g_scores);

    gather_split<<<MTOT, 256>>>(input_text, embed, x_h, x_l);
    split_arr<<<8192, 256>>>(target, T_h, T_l, (size_t)MTOT * EDIM);
    split_arr<<<16384, 256>>>(lin_w, lin_h, lin_l, (size_t)VOC * EDIM);

    const size_t EE = (size_t)EDIM * EDIM;

    for (int l = 0; l < NL; l++) {
        split_arr<<<8192, 256>>>(in_proj_w + (size_t)l * 3 * EE, w_h, w_l, 3 * EE);
        split_arr<<<4096, 256>>>(out_w + (size_t)l * EE, wo_h, wo_l, EE);

        // q = (x @ Wq^T) * SCALE
        launch_gemm(false, x_h, x_l, 0, w_h, w_l, 0,
                    nullptr, q_h, q_l, 0,
                    MTOT, EDIM, EDIM, EDIM, SCALE_Q, nullptr, 1);
        // k = target @ Wk^T
        launch_gemm(false, T_h, T_l, 0, w_h + EE, w_l + EE, 0,
                    nullptr, k_h, k_l, 0,
                    MTOT, EDIM, EDIM, EDIM, 1.f, nullptr, 1);
        // vT[b] = (target_b @ Wv^T)^T  (transposed store)
        launch_gemm(true, T_h, T_l, (size_t)SKV * EDIM, w_h + 2 * EE, w_l + 2 * EE, 0,
                    nullptr, vT_h, vT_l, (size_t)EDIM * SKV,
                    SKV, EDIM, EDIM, SKV, 1.f, nullptr, NB);
        // scores[b] = q_b @ k_b^T  (fp32)
        launch_gemm(false, q_h, q_l, (size_t)SQ * EDIM, k_h, k_l, (size_t)SKV * EDIM,
                    sc, nullptr, nullptr, (size_t)SQ * SKV,
                    SQ, SKV, EDIM, SKV, 1.f, nullptr, NB);
        softmax_split<<<NB * SQ, 256>>>(sc, p_h, p_l);
        // o[b] = attn_b @ vT_b^T
        launch_gemm(false, p_h, p_l, (size_t)SQ * SKV, vT_h, vT_l, (size_t)EDIM * SKV,
                    nullptr, o_h, o_l, (size_t)SQ * EDIM,
                    SQ, EDIM, SKV, EDIM, 1.f, nullptr, NB);
        // x = o @ out_w^T + out_b
        launch_gemm(false, o_h, o_l, 0, wo_h, wo_l, 0,
                    nullptr, x_h, x_l, 0,
                    MTOT, EDIM, EDIM, EDIM, 1.f, out_b + (size_t)l * EDIM, 1);
    }

    // logits = x @ lin_w^T + lin_b  (fp32 out)
    launch_gemm(false, x_h, x_l, 0, lin_h, lin_l, 0,
                logits, nullptr, nullptr, 0,
                MTOT, VOC, EDIM, VOC, 1.f, lin_b, 1);
}

// round 7
// speedup vs baseline: 2.2272x; 1.1467x over previous
#include <cuda_runtime.h>
#include <cuda_bf16.h>
#include <cstdint>

typedef __nv_bfloat16 bf16;

// ---------------- problem constants ----------------
#define NB    8
#define SQ    1024
#define SKV   1024
#define EDIM  1024
#define VOC   32000
#define NL    6
#define MTOT  (NB * SQ)        // 8192
#define SCALE_Q 0.125f

// ---------------- device scratch ----------------
__device__ bf16  g_x_h [MTOT * EDIM];
__device__ bf16  g_x_l [MTOT * EDIM];
__device__ bf16  g_T_h [MTOT * EDIM];
__device__ bf16  g_T_l [MTOT * EDIM];
__device__ bf16  g_q_h [MTOT * EDIM];
__device__ bf16  g_q_l [MTOT * EDIM];
__device__ bf16  g_k_h [MTOT * EDIM];
__device__ bf16  g_k_l [MTOT * EDIM];
__device__ bf16  g_vT_h[MTOT * EDIM];
__device__ bf16  g_vT_l[MTOT * EDIM];
__device__ bf16  g_p_h [NB * SQ * SKV];
__device__ bf16  g_p_l [NB * SQ * SKV];
__device__ bf16  g_o_h [MTOT * EDIM];
__device__ bf16  g_o_l [MTOT * EDIM];
__device__ float g_scores[NB * SQ * SKV];
__device__ bf16  g_w_h [3 * EDIM * EDIM];
__device__ bf16  g_w_l [3 * EDIM * EDIM];
__device__ bf16  g_wo_h[EDIM * EDIM];
__device__ bf16  g_wo_l[EDIM * EDIM];
__device__ bf16  g_lin_h[VOC * EDIM];
__device__ bf16  g_lin_l[VOC * EDIM];

// ---------------- elementwise helpers ----------------
__device__ __forceinline__ void split2(float v, bf16& h, bf16& l) {
    h = __float2bfloat16(v);
    l = __float2bfloat16(v - __bfloat162float(h));
}

__global__ void split_arr(const float* __restrict__ src, bf16* __restrict__ h,
                          bf16* __restrict__ l, size_t n) {
    size_t stride = (size_t)gridDim.x * blockDim.x;
    for (size_t i = (size_t)blockIdx.x * blockDim.x + threadIdx.x; i < n; i += stride)
        split2(src[i], h[i], l[i]);
}

__global__ void gather_split(const int* __restrict__ idx, const float* __restrict__ embed,
                             bf16* __restrict__ xh, bf16* __restrict__ xl) {
    int row = blockIdx.x;
    int tok = idx[row];
    const float* src = embed + (size_t)tok * EDIM;
    bf16* h = xh + (size_t)row * EDIM;
    bf16* l = xl + (size_t)row * EDIM;
    for (int c = threadIdx.x; c < EDIM; c += blockDim.x)
        split2(src[c], h[c], l[c]);
}

__global__ void softmax_split(const float* __restrict__ S, bf16* __restrict__ Ph,
                              bf16* __restrict__ Pl) {
    int row = blockIdx.x;
    int t = threadIdx.x;
    const float* s = S + (size_t)row * SKV;
    float v[4];
    float lm = -1e30f;
#pragma unroll
    for (int i = 0; i < 4; i++) { v[i] = s[t + i * 256]; lm = fmaxf(lm, v[i]); }
    __shared__ float red[256];
    red[t] = lm; __syncthreads();
#pragma unroll
    for (int off = 128; off > 0; off >>= 1) {
        if (t < off) red[t] = fmaxf(red[t], red[t + off]);
        __syncthreads();
    }
    float mx = red[0];
    __syncthreads();
    float ls = 0.f;
#pragma unroll
    for (int i = 0; i < 4; i++) { v[i] = __expf(v[i] - mx); ls += v[i]; }
    red[t] = ls; __syncthreads();
#pragma unroll
    for (int off = 128; off > 0; off >>= 1) {
        if (t < off) red[t] += red[t + off];
        __syncthreads();
    }
    float inv = 1.f / red[0];
    bf16* ph = Ph + (size_t)row * SKV;
    bf16* pl = Pl + (size_t)row * SKV;
#pragma unroll
    for (int i = 0; i < 4; i++) {
        bf16 h, l;
        split2(v[i] * inv, h, l);
        ph[t + i * 256] = h;
        pl[t + i * 256] = l;
    }
}

// ---------------- mma.sync GEMM, 256x128x32 tile ----------------
// C[m,n] = alpha * sum_k A[m,k]*B[n,k] (+ bias[n]); 3-term bf16 hi/lo, fp32 acc.
// 256 threads = 8 warps as 4(m) x 2(n); warp tile 64x64. 3-stage cp.async.

#define BK        32
#define BM        256
#define BN        128
#define LDROW     80                        // padded row pitch (bytes) for 32 bf16
#define A_BYTES   (BM * LDROW)              // 20480 per split array
#define B_BYTES   (BN * LDROW)              // 10240 per split array
#define STAGE_B   (2 * A_BYTES + 2 * B_BYTES) // 61440
#define NSTAGE    3
#define GSMEM     (NSTAGE * STAGE_B)        // 184320
#define GROUP_Y   8

__device__ __forceinline__ uint32_t smem_u32(const void* p) {
    uint32_t a;
    asm("{ .reg .u64 t; cvta.to.shared.u64 t, %1; cvt.u32.u64 %0, t; }" : "=r"(a) : "l"(p));
    return a;
}

__device__ __forceinline__ void ldm_x4(uint32_t& r0, uint32_t& r1, uint32_t& r2,
                                       uint32_t& r3, uint32_t addr) {
    asm volatile("ldmatrix.sync.aligned.m8n8.x4.shared.b16 {%0,%1,%2,%3}, [%4];"
                 : "=r"(r0), "=r"(r1), "=r"(r2), "=r"(r3) : "r"(addr));
}

__device__ __forceinline__ void mma16816(float* c, const uint32_t* a, const uint32_t* b) {
    asm volatile(
        "mma.sync.aligned.m16n8k16.row.col.f32.bf16.bf16.f32 "
        "{%0,%1,%2,%3}, {%4,%5,%6,%7}, {%8,%9}, {%0,%1,%2,%3};"
        : "+f"(c[0]), "+f"(c[1]), "+f"(c[2]), "+f"(c[3])
        : "r"(a[0]), "r"(a[1]), "r"(a[2]), "r"(a[3]), "r"(b[0]), "r"(b[1]));
}

__device__ __forceinline__ void fill_stage(uint32_t sbase,
    const bf16* __restrict__ A0, const bf16* __restrict__ A1,
    const bf16* __restrict__ B0, const bf16* __restrict__ B1,
    int K, int k0, int tid)
{
    // A arrays: 256 rows x 4 chunks of 16B = 1024 entries each
#pragma unroll
    for (int j = 0; j < 4; j++) {
        int e = tid + j * 256;
        int row = e >> 2, c = e & 3;
        uint32_t dA = sbase + row * LDROW + c * 16;
        uint64_t sh = __cvta_generic_to_global((const void*)(A0 + (size_t)row * K + k0 + c * 8));
        uint64_t sl = __cvta_generic_to_global((const void*)(A1 + (size_t)row * K + k0 + c * 8));
        asm volatile("cp.async.cg.shared.global [%0], [%1], 16;" :: "r"(dA), "l"(sh));
        asm volatile("cp.async.cg.shared.global [%0], [%1], 16;" :: "r"(dA + A_BYTES), "l"(sl));
    }
    // B arrays: 128 rows x 4 chunks = 512 entries each
#pragma unroll
    for (int j = 0; j < 2; j++) {
        int e = tid + j * 256;
        int row = e >> 2, c = e & 3;
        uint32_t dB = sbase + 2 * A_BYTES + row * LDROW + c * 16;
        uint64_t sh = __cvta_generic_to_global((const void*)(B0 + (size_t)row * K + k0 + c * 8));
        uint64_t sl = __cvta_generic_to_global((const void*)(B1 + (size_t)row * K + k0 + c * 8));
        asm volatile("cp.async.cg.shared.global [%0], [%1], 16;" :: "r"(dB), "l"(sh));
        asm volatile("cp.async.cg.shared.global [%0], [%1], 16;" :: "r"(dB + B_BYTES), "l"(sl));
    }
    asm volatile("cp.async.commit_group;" ::: "memory");
}

template <bool TRANS>
__global__ void __launch_bounds__(256, 1)
gemm_mma(const bf16* __restrict__ Ah, const bf16* __restrict__ Al, size_t sA,
         const bf16* __restrict__ Bh, const bf16* __restrict__ Bl, size_t sB,
         float* __restrict__ Cf, bf16* __restrict__ Ch, bf16* __restrict__ Cl, size_t sC,
         int M, int N, int K, int ldc, float alpha, const float* __restrict__ bias)
{
    extern __shared__ __align__(128) char smem[];
    const uint32_t sb = smem_u32(smem);
    const int tid  = threadIdx.x;
    const int wid  = tid >> 5;
    const int lane = tid & 31;
    const int wm = wid >> 1;                  // 0..3 : 64-row block
    const int wn = wid & 1;                   // 0..1 : 64-col block
    const int z  = blockIdx.z;

    // grouped rasterization (compact waves -> less DRAM re-read of B)
    int lin = blockIdx.y * gridDim.x + blockIdx.x;
    int gsz = GROUP_Y * gridDim.x;
    int grp = lin / gsz, rem = lin % gsz;
    int span = min(GROUP_Y, (int)gridDim.y - grp * GROUP_Y);
    int by = grp * GROUP_Y + rem % span;
    int bx = rem / span;
    const int m0 = by * BM;
    const int n0 = bx * BN;

    const bf16* A0 = Ah + (size_t)z * sA + (size_t)m0 * K;
    const bf16* A1 = Al + (size_t)z * sA + (size_t)m0 * K;
    const bf16* B0 = Bh + (size_t)z * sB + (size_t)n0 * K;
    const bf16* B1 = Bl + (size_t)z * sB + (size_t)n0 * K;

    // per-thread ldmatrix base offsets (bytes) within a split array
    const uint32_t a_base = (uint32_t)((wm * 64 + (lane & 15)) * LDROW + (lane >> 4) * 16);
    const uint32_t b_base = (uint32_t)((wn * 64 + (lane >> 4) * 8 + (lane & 7)) * LDROW
                                       + ((lane >> 3) & 1) * 16);

    float acc[4][8][4];
#pragma unroll
    for (int i = 0; i < 4; i++)
#pragma unroll
        for (int j = 0; j < 8; j++)
#pragma unroll
            for (int r = 0; r < 4; r++) acc[i][j][r] = 0.f;

    const int KT = K / BK;

    fill_stage(sb + 0 * STAGE_B, A0, A1, B0, B1, K, 0, tid);
    fill_stage(sb + 1 * STAGE_B, A0, A1, B0, B1, K, BK, tid);

    int stage = 0;
    for (int kt = 0; kt < KT; kt++) {
        asm volatile("cp.async.wait_group 1;" ::: "memory");
        __syncthreads();

        int f = kt + 2;
        if (f < KT) {
            int fs = f % NSTAGE;
            fill_stage(sb + fs * STAGE_B, A0, A1, B0, B1, K, f * BK, tid);
        } else {
            asm volatile("cp.async.commit_group;" ::: "memory");
        }

        const uint32_t sAh = sb + stage * STAGE_B;
        const uint32_t sAl = sAh + A_BYTES;
        const uint32_t sBh = sAh + 2 * A_BYTES;
        const uint32_t sBl = sBh + B_BYTES;

#pragma unroll
        for (int ks = 0; ks < 2; ks++) {
            const uint32_t ko = ks * 32;      // 16 bf16 = 32 bytes
            uint32_t ah[4][4], al[4][4], bh[8][2], bl[8][2];
#pragma unroll
            for (int mi = 0; mi < 4; mi++) {
                uint32_t off = a_base + mi * 16 * LDROW + ko;
                ldm_x4(ah[mi][0], ah[mi][1], ah[mi][2], ah[mi][3], sAh + off);
                ldm_x4(al[mi][0], al[mi][1], al[mi][2], al[mi][3], sAl + off);
            }
#pragma unroll
            for (int p = 0; p < 4; p++) {     // each x4 covers two n8 blocks
                uint32_t off = b_base + p * 16 * LDROW + ko;
                ldm_x4(bh[2 * p][0], bh[2 * p][1], bh[2 * p + 1][0], bh[2 * p + 1][1], sBh + off);
                ldm_x4(bl[2 * p][0], bl[2 * p][1], bl[2 * p + 1][0], bl[2 * p + 1][1], sBl + off);
            }
#pragma unroll
            for (int mi = 0; mi < 4; mi++)
#pragma unroll
                for (int ni = 0; ni < 8; ni++) {
                    mma16816(acc[mi][ni], ah[mi], bh[ni]);
                    mma16816(acc[mi][ni], ah[mi], bl[ni]);
                    mma16816(acc[mi][ni], al[mi], bh[ni]);
                }
        }
        stage = (stage + 1 == NSTAGE) ? 0 : stage + 1;
    }

    asm volatile("cp.async.wait_group 0;" ::: "memory");
    __syncthreads();

    // ---------------- epilogue ----------------
    // non-TRANS: SE[256][132] ; TRANS: SE[128][260] (stored already transposed)
    const int LD = TRANS ? 260 : 132;
    float* SE = reinterpret_cast<float*>(smem);
    const int tr = lane >> 2;                 // 0..7
    const int tc = (lane & 3) * 2;            // 0,2,4,6
#pragma unroll
    for (int mi = 0; mi < 4; mi++)
#pragma unroll
        for (int ni = 0; ni < 8; ni++) {
            int r0 = wm * 64 + mi * 16 + tr;
            int c0 = wn * 64 + ni * 8 + tc;
            if (!TRANS) {
                SE[r0 * LD + c0]           = acc[mi][ni][0];
                SE[r0 * LD + c0 + 1]       = acc[mi][ni][1];
                SE[(r0 + 8) * LD + c0]     = acc[mi][ni][2];
                SE[(r0 + 8) * LD + c0 + 1] = acc[mi][ni][3];
            } else {
                SE[c0 * LD + r0]           = acc[mi][ni][0];
                SE[(c0 + 1) * LD + r0]     = acc[mi][ni][1];
                SE[c0 * LD + r0 + 8]       = acc[mi][ni][2];
                SE[(c0 + 1) * LD + r0 + 8] = acc[mi][ni][3];
            }
        }
    __syncthreads();

    // coalesced write: SE is [outer][inner]; out[(OB+outer)*ldc + IB+inner]
    const int INNER4 = TRANS ? 64 : 32;       // inner dim / 4
    const int OB = TRANS ? n0 : m0;
    const int IB = TRANS ? m0 : n0;
#pragma unroll
    for (int i = 0; i < 32; i++) {
        int e = tid + i * 256;                // 0..8191 float4s
        int row = e / INNER4;
        int c4 = (e % INNER4) * 4;
        float4 v = *reinterpret_cast<float4*>(&SE[row * LD + c4]);
        v.x *= alpha; v.y *= alpha; v.z *= alpha; v.w *= alpha;
        if (!TRANS && bias) {
            v.x += bias[n0 + c4];
            v.y += bias[n0 + c4 + 1];
            v.z += bias[n0 + c4 + 2];
            v.w += bias[n0 + c4 + 3];
        }
        size_t o = (size_t)z * sC + (size_t)(OB + row) * ldc + IB + c4;
        if (Cf) *reinterpret_cast<float4*>(Cf + o) = v;
        if (Ch) {
            bf16 h0, l0, h1, l1, h2, l2, h3, l3;
            split2(v.x, h0, l0); split2(v.y, h1, l1);
            split2(v.z, h2, l2); split2(v.w, h3, l3);
            __nv_bfloat162 hp0 = {h0, h1}, hp1 = {h2, h3};
            __nv_bfloat162 lp0 = {l0, l1}, lp1 = {l2, l3};
            uint2 hu = make_uint2(*(uint32_t*)&hp0, *(uint32_t*)&hp1);
            uint2 lu = make_uint2(*(uint32_t*)&lp0, *(uint32_t*)&lp1);
            *reinterpret_cast<uint2*>(Ch + o) = hu;
            *reinterpret_cast<uint2*>(Cl + o) = lu;
        }
    }
}

// ---------------- host-side launcher ----------------
static void launch_gemm(bool trans,
                        const bf16* Ah, const bf16* Al, size_t sA,
                        const bf16* Bh, const bf16* Bl, size_t sB,
                        float* Cf, bf16* Ch, bf16* Cl, size_t sC,
                        int M, int N, int K, int ldc, float alpha,
                        const float* bias, int batch) {
    dim3 grid(N / BN, M / BM, batch);
    if (trans)
        gemm_mma<true><<<grid, 256, GSMEM>>>(Ah, Al, sA, Bh, Bl, sB, Cf, Ch, Cl, sC,
                                             M, N, K, ldc, alpha, bias);
    else
        gemm_mma<false><<<grid, 256, GSMEM>>>(Ah, Al, sA, Bh, Bl, sB, Cf, Ch, Cl, sC,
                                              M, N, K, ldc, alpha, bias);
}

#define SYM(var, sym)                                   \
    do {                                                \
        void* _p = nullptr;                             \
        cudaGetSymbolAddress(&_p, sym);                 \
        var = (decltype(var))_p;                        \
    } while (0)

extern "C" void kernel_launch(void* const* d_in, const int* in_sizes, int n_in,
                              void* d_out, int out_size) {
    const int*   input_text = (const int*)d_in[0];
    const float* target     = (const float*)d_in[1];
    const float* embed      = (const float*)d_in[2];
    const float* in_proj_w  = (const float*)d_in[3];
    const float* out_w      = (const float*)d_in[4];
    const float* out_b      = (const float*)d_in[5];
    const float* lin_w      = (const float*)d_in[6];
    const float* lin_b      = (const float*)d_in[7];
    float*       logits     = (float*)d_out;

    cudaFuncSetAttribute(gemm_mma<false>, cudaFuncAttributeMaxDynamicSharedMemorySize, GSMEM);
    cudaFuncSetAttribute(gemm_mma<true>,  cudaFuncAttributeMaxDynamicSharedMemorySize, GSMEM);

    bf16 *x_h, *x_l, *T_h, *T_l, *q_h, *q_l, *k_h, *k_l, *vT_h, *vT_l;
    bf16 *p_h, *p_l, *o_h, *o_l, *w_h, *w_l, *wo_h, *wo_l, *lin_h, *lin_l;
    float* sc;
    SYM(x_h, g_x_h);   SYM(x_l, g_x_l);
    SYM(T_h, g_T_h);   SYM(T_l, g_T_l);
    SYM(q_h, g_q_h);   SYM(q_l, g_q_l);
    SYM(k_h, g_k_h);   SYM(k_l, g_k_l);
    SYM(vT_h, g_vT_h); SYM(vT_l, g_vT_l);
    SYM(p_h, g_p_h);   SYM(p_l, g_p_l);
    SYM(o_h, g_o_h);   SYM(o_l, g_o_l);
    SYM(w_h, g_w_h);   SYM(w_l, g_w_l);
    SYM(wo_h, g_wo_h); SYM(wo_l, g_wo_l);
    SYM(lin_h, g_lin_h); SYM(lin_l, g_lin_l);
    SYM(sc, g_scores);

    // (lin_w split moved later so ncu's skip-5 lands on a GEMM launch)
    gather_split<<<MTOT, 256>>>(input_text, embed, x_h, x_l);
    split_arr<<<8192, 256>>>(target, T_h, T_l, (size_t)MTOT * EDIM);

    const size_t EE = (size_t)EDIM * EDIM;

    for (int l = 0; l < NL; l++) {
        split_arr<<<8192, 256>>>(in_proj_w + (size_t)l * 3 * EE, w_h, w_l, 3 * EE);
        split_arr<<<4096, 256>>>(out_w + (size_t)l * EE, wo_h, wo_l, EE);

        // q = (x @ Wq^T) * SCALE
        launch_gemm(false, x_h, x_l, 0, w_h, w_l, 0,
                    nullptr, q_h, q_l, 0,
                    MTOT, EDIM, EDIM, EDIM, SCALE_Q, nullptr, 1);
        // k = target @ Wk^T
        launch_gemm(false, T_h, T_l, 0, w_h + EE, w_l + EE, 0,
                    nullptr, k_h, k_l, 0,
                    MTOT, EDIM, EDIM, EDIM, 1.f, nullptr, 1);
        // vT[b] = (target_b @ Wv^T)^T  (transposed store)
        launch_gemm(true, T_h, T_l, (size_t)SKV * EDIM, w_h + 2 * EE, w_l + 2 * EE, 0,
                    nullptr, vT_h, vT_l, (size_t)EDIM * SKV,
                    SKV, EDIM, EDIM, SKV, 1.f, nullptr, NB);
        // scores[b] = q_b @ k_b^T  (fp32)
        launch_gemm(false, q_h, q_l, (size_t)SQ * EDIM, k_h, k_l, (size_t)SKV * EDIM,
                    sc, nullptr, nullptr, (size_t)SQ * SKV,
                    SQ, SKV, EDIM, SKV, 1.f, nullptr, NB);
        softmax_split<<<NB * SQ, 256>>>(sc, p_h, p_l);
        // o[b] = attn_b @ vT_b^T
        launch_gemm(false, p_h, p_l, (size_t)SQ * SKV, vT_h, vT_l, (size_t)EDIM * SKV,
                    nullptr, o_h, o_l, (size_t)SQ * EDIM,
                    SQ, EDIM, SKV, EDIM, 1.f, nullptr, NB);
        // x = o @ out_w^T + out_b
        launch_gemm(false, o_h, o_l, 0, wo_h, wo_l, 0,
                    nullptr, x_h, x_l, 0,
                    MTOT, EDIM, EDIM, EDIM, 1.f, out_b + (size_t)l * EDIM, 1);
    }

    // lin_w split just before use
    split_arr<<<16384, 256>>>(lin_w, lin_h, lin_l, (size_t)VOC * EDIM);
    // logits = x @ lin_w^T + lin_b  (fp32 out)
    launch_gemm(false, x_h, x_l, 0, lin_h, lin_l, 0,
                logits, nullptr, nullptr, 0,
                MTOT, VOC, EDIM, VOC, 1.f, lin_b, 1);
}

// round 8
// speedup vs baseline: 3.1208x; 1.4012x over previous
#include <cuda_runtime.h>
#include <cuda_fp16.h>
#include <cstdint>

typedef __half h16;

// ---------------- problem constants ----------------
#define NB    8
#define SQ    1024
#define SKV   1024
#define EDIM  1024
#define VOC   32000
#define NL    6
#define MTOT  (NB * SQ)        // 8192
#define SCALE_Q 0.125f

// ---------------- device scratch ----------------
// hi-only activations (A-side operands)
__device__ __align__(16) h16  g_x  [MTOT * EDIM];
__device__ __align__(16) h16  g_T  [MTOT * EDIM];
__device__ __align__(16) h16  g_q  [MTOT * EDIM];
__device__ __align__(16) h16  g_p  [NB * SQ * SKV];
__device__ __align__(16) h16  g_o  [MTOT * EDIM];
// hi+lo (B-side operands)
__device__ __align__(16) h16  g_k_h [MTOT * EDIM];
__device__ __align__(16) h16  g_k_l [MTOT * EDIM];
__device__ __align__(16) h16  g_vT_h[MTOT * EDIM];
__device__ __align__(16) h16  g_vT_l[MTOT * EDIM];
__device__ __align__(16) h16  g_w_h [3 * EDIM * EDIM];
__device__ __align__(16) h16  g_w_l [3 * EDIM * EDIM];
__device__ __align__(16) h16  g_wo_h[EDIM * EDIM];
__device__ __align__(16) h16  g_wo_l[EDIM * EDIM];
__device__ __align__(16) h16  g_lin_h[VOC * EDIM];
__device__ __align__(16) h16  g_lin_l[VOC * EDIM];
__device__ float g_scores[NB * SQ * SKV];

// ---------------- helpers ----------------
__device__ __forceinline__ void split2h(float v, h16& h, h16& l) {
    h = __float2half_rn(v);
    l = __float2half_rn(v - __half2float(h));
}
__device__ __forceinline__ uint32_t pack2(h16 a, h16 b) {
    __half2 p = __halves2half2(a, b);
    return *reinterpret_cast<uint32_t*>(&p);
}

// fp32 -> fp16 hi+lo, vectorized (n4 = count of float4)
__global__ void split_h(const float* __restrict__ src, h16* __restrict__ h,
                        h16* __restrict__ l, size_t n4) {
    size_t stride = (size_t)gridDim.x * blockDim.x;
    for (size_t i = (size_t)blockIdx.x * blockDim.x + threadIdx.x; i < n4; i += stride) {
        float4 v = reinterpret_cast<const float4*>(src)[i];
        h16 h0, l0, h1, l1, h2, l2, h3, l3;
        split2h(v.x, h0, l0); split2h(v.y, h1, l1);
        split2h(v.z, h2, l2); split2h(v.w, h3, l3);
        reinterpret_cast<uint2*>(h)[i] = make_uint2(pack2(h0, h1), pack2(h2, h3));
        reinterpret_cast<uint2*>(l)[i] = make_uint2(pack2(l0, l1), pack2(l2, l3));
    }
}

// fp32 -> fp16 hi only, vectorized
__global__ void conv_h(const float* __restrict__ src, h16* __restrict__ h, size_t n4) {
    size_t stride = (size_t)gridDim.x * blockDim.x;
    for (size_t i = (size_t)blockIdx.x * blockDim.x + threadIdx.x; i < n4; i += stride) {
        float4 v = reinterpret_cast<const float4*>(src)[i];
        reinterpret_cast<uint2*>(h)[i] =
            make_uint2(pack2(__float2half_rn(v.x), __float2half_rn(v.y)),
                       pack2(__float2half_rn(v.z), __float2half_rn(v.w)));
    }
}

// embedding gather -> fp16 hi; one block (256 thr) per row, 4 cols/thread
__global__ void gather_h(const int* __restrict__ idx, const float* __restrict__ embed,
                         h16* __restrict__ x) {
    int row = blockIdx.x;
    int tok = idx[row];
    const float4* src = reinterpret_cast<const float4*>(embed + (size_t)tok * EDIM);
    float4 v = src[threadIdx.x];
    reinterpret_cast<uint2*>(x + (size_t)row * EDIM)[threadIdx.x] =
        make_uint2(pack2(__float2half_rn(v.x), __float2half_rn(v.y)),
                   pack2(__float2half_rn(v.z), __float2half_rn(v.w)));
}

// row softmax over 1024 cols -> fp16; 256 threads/row, float4 IO, shfl reductions
__global__ void softmax_h(const float* __restrict__ S, h16* __restrict__ P) {
    int row = blockIdx.x;
    int t = threadIdx.x;
    int lane = t & 31, w = t >> 5;
    float4 v = reinterpret_cast<const float4*>(S + (size_t)row * SKV)[t];

    float m = fmaxf(fmaxf(v.x, v.y), fmaxf(v.z, v.w));
#pragma unroll
    for (int off = 16; off > 0; off >>= 1)
        m = fmaxf(m, __shfl_xor_sync(0xFFFFFFFFu, m, off));
    __shared__ float red[8];
    if (lane == 0) red[w] = m;
    __syncthreads();
    float mx = red[0];
#pragma unroll
    for (int i = 1; i < 8; i++) mx = fmaxf(mx, red[i]);

    v.x = __expf(v.x - mx); v.y = __expf(v.y - mx);
    v.z = __expf(v.z - mx); v.w = __expf(v.w - mx);
    float s = v.x + v.y + v.z + v.w;
#pragma unroll
    for (int off = 16; off > 0; off >>= 1)
        s += __shfl_xor_sync(0xFFFFFFFFu, s, off);
    __shared__ float red2[8];
    if (lane == 0) red2[w] = s;
    __syncthreads();
    float tot = red2[0];
#pragma unroll
    for (int i = 1; i < 8; i++) tot += red2[i];
    float inv = 1.f / tot;

    reinterpret_cast<uint2*>(P + (size_t)row * SKV)[t] =
        make_uint2(pack2(__float2half_rn(v.x * inv), __float2half_rn(v.y * inv)),
                   pack2(__float2half_rn(v.z * inv), __float2half_rn(v.w * inv)));
}

// ---------------- mma.sync fp16 GEMM, 256x128x32 tile, 2-term split ----------------
// C[m,n] = alpha * sum_k A[m,k]*(Bh[n,k]+Bl[n,k]) + bias[n]
// 256 threads = 8 warps (4m x 2n), warp tile 64x64, 4-stage cp.async.

#define BK        32
#define BM        256
#define BN        128
#define LDROW     80                          // padded row pitch (bytes), 32 fp16 + pad
#define A_BYTES   (BM * LDROW)                // 20480
#define B_BYTES   (BN * LDROW)                // 10240
#define STAGE_B   (A_BYTES + 2 * B_BYTES)     // 40960
#define NSTAGE    4
#define GSMEM     (NSTAGE * STAGE_B)          // 163840
#define GROUP_Y   8

__device__ __forceinline__ uint32_t smem_u32(const void* p) {
    uint32_t a;
    asm("{ .reg .u64 t; cvta.to.shared.u64 t, %1; cvt.u32.u64 %0, t; }" : "=r"(a) : "l"(p));
    return a;
}

__device__ __forceinline__ void ldm_x4(uint32_t& r0, uint32_t& r1, uint32_t& r2,
                                       uint32_t& r3, uint32_t addr) {
    asm volatile("ldmatrix.sync.aligned.m8n8.x4.shared.b16 {%0,%1,%2,%3}, [%4];"
                 : "=r"(r0), "=r"(r1), "=r"(r2), "=r"(r3) : "r"(addr));
}

__device__ __forceinline__ void mma16816(float* c, const uint32_t* a, const uint32_t* b) {
    asm volatile(
        "mma.sync.aligned.m16n8k16.row.col.f32.f16.f16.f32 "
        "{%0,%1,%2,%3}, {%4,%5,%6,%7}, {%8,%9}, {%0,%1,%2,%3};"
        : "+f"(c[0]), "+f"(c[1]), "+f"(c[2]), "+f"(c[3])
        : "r"(a[0]), "r"(a[1]), "r"(a[2]), "r"(a[3]), "r"(b[0]), "r"(b[1]));
}

__device__ __forceinline__ void fill_stage(uint32_t sbase,
    const h16* __restrict__ A0, const h16* __restrict__ B0, const h16* __restrict__ B1,
    int K, int k0, int tid)
{
    // A: 256 rows x 4 chunks of 16B = 1024 tasks
#pragma unroll
    for (int j = 0; j < 4; j++) {
        int e = tid + j * 256;
        int row = e >> 2, c = e & 3;
        uint32_t dst = sbase + row * LDROW + c * 16;
        uint64_t src = __cvta_generic_to_global((const void*)(A0 + (size_t)row * K + k0 + c * 8));
        asm volatile("cp.async.cg.shared.global [%0], [%1], 16;" :: "r"(dst), "l"(src));
    }
    // Bh, Bl: 128 rows x 4 chunks = 512 tasks each
#pragma unroll
    for (int j = 0; j < 2; j++) {
        int e = tid + j * 256;
        int row = e >> 2, c = e & 3;
        uint32_t dst = sbase + A_BYTES + row * LDROW + c * 16;
        uint64_t sh = __cvta_generic_to_global((const void*)(B0 + (size_t)row * K + k0 + c * 8));
        uint64_t sl = __cvta_generic_to_global((const void*)(B1 + (size_t)row * K + k0 + c * 8));
        asm volatile("cp.async.cg.shared.global [%0], [%1], 16;" :: "r"(dst), "l"(sh));
        asm volatile("cp.async.cg.shared.global [%0], [%1], 16;" :: "r"(dst + B_BYTES), "l"(sl));
    }
    asm volatile("cp.async.commit_group;" ::: "memory");
}

template <bool TRANS>
__global__ void __launch_bounds__(256, 1)
gemm_mma(const h16* __restrict__ A, size_t sA,
         const h16* __restrict__ Bh, const h16* __restrict__ Bl, size_t sB,
         float* __restrict__ Cf, h16* __restrict__ Ch, h16* __restrict__ Cl, size_t sC,
         int M, int N, int K, int ldc, float alpha, const float* __restrict__ bias)
{
    extern __shared__ __align__(128) char smem[];
    const uint32_t sb = smem_u32(smem);
    const int tid  = threadIdx.x;
    const int wid  = tid >> 5;
    const int lane = tid & 31;
    const int wm = wid >> 1;                  // 0..3
    const int wn = wid & 1;                   // 0..1
    const int z  = blockIdx.z;

    // grouped rasterization
    int lin = blockIdx.y * gridDim.x + blockIdx.x;
    int gsz = GROUP_Y * gridDim.x;
    int grp = lin / gsz, rem = lin % gsz;
    int span = min(GROUP_Y, (int)gridDim.y - grp * GROUP_Y);
    int by = grp * GROUP_Y + rem % span;
    int bx = rem / span;
    const int m0 = by * BM;
    const int n0 = bx * BN;

    const h16* A0 = A  + (size_t)z * sA + (size_t)m0 * K;
    const h16* B0 = Bh + (size_t)z * sB + (size_t)n0 * K;
    const h16* B1 = Bl + (size_t)z * sB + (size_t)n0 * K;

    const uint32_t a_base = (uint32_t)((wm * 64 + (lane & 15)) * LDROW + (lane >> 4) * 16);
    const uint32_t b_base = (uint32_t)((wn * 64 + (lane >> 4) * 8 + (lane & 7)) * LDROW
                                       + ((lane >> 3) & 1) * 16);

    float acc[4][8][4];
#pragma unroll
    for (int i = 0; i < 4; i++)
#pragma unroll
        for (int j = 0; j < 8; j++)
#pragma unroll
            for (int r = 0; r < 4; r++) acc[i][j][r] = 0.f;

    const int KT = K / BK;

    fill_stage(sb + 0 * STAGE_B, A0, B0, B1, K, 0, tid);
    fill_stage(sb + 1 * STAGE_B, A0, B0, B1, K, BK, tid);
    fill_stage(sb + 2 * STAGE_B, A0, B0, B1, K, 2 * BK, tid);

    int stage = 0;
    for (int kt = 0; kt < KT; kt++) {
        asm volatile("cp.async.wait_group 2;" ::: "memory");
        __syncthreads();

        int f = kt + 3;
        if (f < KT)
            fill_stage(sb + (f % NSTAGE) * STAGE_B, A0, B0, B1, K, f * BK, tid);

        const uint32_t sA_ = sb + stage * STAGE_B;
        const uint32_t sBh = sA_ + A_BYTES;
        const uint32_t sBl = sBh + B_BYTES;

#pragma unroll
        for (int ks = 0; ks < 2; ks++) {
            const uint32_t ko = ks * 32;
            uint32_t ah[4][4], bh[8][2], bl[8][2];
#pragma unroll
            for (int mi = 0; mi < 4; mi++) {
                uint32_t off = a_base + mi * 16 * LDROW + ko;
                ldm_x4(ah[mi][0], ah[mi][1], ah[mi][2], ah[mi][3], sA_ + off);
            }
#pragma unroll
            for (int p = 0; p < 4; p++) {
                uint32_t off = b_base + p * 16 * LDROW + ko;
                ldm_x4(bh[2 * p][0], bh[2 * p][1], bh[2 * p + 1][0], bh[2 * p + 1][1], sBh + off);
                ldm_x4(bl[2 * p][0], bl[2 * p][1], bl[2 * p + 1][0], bl[2 * p + 1][1], sBl + off);
            }
#pragma unroll
            for (int mi = 0; mi < 4; mi++)
#pragma unroll
                for (int ni = 0; ni < 8; ni++) {
                    mma16816(acc[mi][ni], ah[mi], bh[ni]);
                    mma16816(acc[mi][ni], ah[mi], bl[ni]);
                }
        }
        stage = (stage + 1 == NSTAGE) ? 0 : stage + 1;
    }

    asm volatile("cp.async.wait_group 0;" ::: "memory");
    __syncthreads();

    // ---------------- epilogue ----------------
    const int LD = TRANS ? 260 : 132;
    float* SE = reinterpret_cast<float*>(smem);
    const int tr = lane >> 2;
    const int tc = (lane & 3) * 2;
#pragma unroll
    for (int mi = 0; mi < 4; mi++)
#pragma unroll
        for (int ni = 0; ni < 8; ni++) {
            int r0 = wm * 64 + mi * 16 + tr;
            int c0 = wn * 64 + ni * 8 + tc;
            if (!TRANS) {
                SE[r0 * LD + c0]           = acc[mi][ni][0];
                SE[r0 * LD + c0 + 1]       = acc[mi][ni][1];
                SE[(r0 + 8) * LD + c0]     = acc[mi][ni][2];
                SE[(r0 + 8) * LD + c0 + 1] = acc[mi][ni][3];
            } else {
                SE[c0 * LD + r0]           = acc[mi][ni][0];
                SE[(c0 + 1) * LD + r0]     = acc[mi][ni][1];
                SE[c0 * LD + r0 + 8]       = acc[mi][ni][2];
                SE[(c0 + 1) * LD + r0 + 8] = acc[mi][ni][3];
            }
        }
    __syncthreads();

    const int INNER4 = TRANS ? 64 : 32;
    const int OB = TRANS ? n0 : m0;
    const int IB = TRANS ? m0 : n0;
#pragma unroll
    for (int i = 0; i < 32; i++) {
        int e = tid + i * 256;
        int row = e / INNER4;
        int c4 = (e % INNER4) * 4;
        float4 v = *reinterpret_cast<float4*>(&SE[row * LD + c4]);
        v.x *= alpha; v.y *= alpha; v.z *= alpha; v.w *= alpha;
        if (!TRANS && bias) {
            v.x += bias[n0 + c4];
            v.y += bias[n0 + c4 + 1];
            v.z += bias[n0 + c4 + 2];
            v.w += bias[n0 + c4 + 3];
        }
        size_t o = (size_t)z * sC + (size_t)(OB + row) * ldc + IB + c4;
        if (Cf) *reinterpret_cast<float4*>(Cf + o) = v;
        if (Ch) {
            if (Cl) {
                h16 h0, l0, h1, l1, h2, l2, h3, l3;
                split2h(v.x, h0, l0); split2h(v.y, h1, l1);
                split2h(v.z, h2, l2); split2h(v.w, h3, l3);
                *reinterpret_cast<uint2*>(Ch + o) = make_uint2(pack2(h0, h1), pack2(h2, h3));
                *reinterpret_cast<uint2*>(Cl + o) = make_uint2(pack2(l0, l1), pack2(l2, l3));
            } else {
                *reinterpret_cast<uint2*>(Ch + o) =
                    make_uint2(pack2(__float2half_rn(v.x), __float2half_rn(v.y)),
                               pack2(__float2half_rn(v.z), __float2half_rn(v.w)));
            }
        }
    }
}

// ---------------- host-side launcher ----------------
static void launch_gemm(bool trans,
                        const h16* A, size_t sA,
                        const h16* Bh, const h16* Bl, size_t sB,
                        float* Cf, h16* Ch, h16* Cl, size_t sC,
                        int M, int N, int K, int ldc, float alpha,
                        const float* bias, int batch) {
    dim3 grid(N / BN, M / BM, batch);
    if (trans)
        gemm_mma<true><<<grid, 256, GSMEM>>>(A, sA, Bh, Bl, sB, Cf, Ch, Cl, sC,
                                             M, N, K, ldc, alpha, bias);
    else
        gemm_mma<false><<<grid, 256, GSMEM>>>(A, sA, Bh, Bl, sB, Cf, Ch, Cl, sC,
                                              M, N, K, ldc, alpha, bias);
}

#define SYM(var, sym)                                   \
    do {                                                \
        void* _p = nullptr;                             \
        cudaGetSymbolAddress(&_p, sym);                 \
        var = (decltype(var))_p;                        \
    } while (0)

extern "C" void kernel_launch(void* const* d_in, const int* in_sizes, int n_in,
                              void* d_out, int out_size) {
    const int*   input_text = (const int*)d_in[0];
    const float* target     = (const float*)d_in[1];
    const float* embed      = (const float*)d_in[2];
    const float* in_proj_w  = (const float*)d_in[3];
    const float* out_w      = (const float*)d_in[4];
    const float* out_b      = (const float*)d_in[5];
    const float* lin_w      = (const float*)d_in[6];
    const float* lin_b      = (const float*)d_in[7];
    float*       logits     = (float*)d_out;

    cudaFuncSetAttribute(gemm_mma<false>, cudaFuncAttributeMaxDynamicSharedMemorySize, GSMEM);
    cudaFuncSetAttribute(gemm_mma<true>,  cudaFuncAttributeMaxDynamicSharedMemorySize, GSMEM);

    h16 *x, *T, *q, *p, *o, *k_h, *k_l, *vT_h, *vT_l;
    h16 *w_h, *w_l, *wo_h, *wo_l, *lin_h, *lin_l;
    float* sc;
    SYM(x, g_x);   SYM(T, g_T);   SYM(q, g_q);   SYM(p, g_p);   SYM(o, g_o);
    SYM(k_h, g_k_h);   SYM(k_l, g_k_l);
    SYM(vT_h, g_vT_h); SYM(vT_l, g_vT_l);
    SYM(w_h, g_w_h);   SYM(w_l, g_w_l);
    SYM(wo_h, g_wo_h); SYM(wo_l, g_wo_l);
    SYM(lin_h, g_lin_h); SYM(lin_l, g_lin_l);
    SYM(sc, g_scores);

    gather_h<<<MTOT, 256>>>(input_text, embed, x);
    conv_h<<<4096, 256>>>(target, T, (size_t)MTOT * EDIM / 4);

    const size_t EE = (size_t)EDIM * EDIM;

    for (int l = 0; l < NL; l++) {
        split_h<<<3072, 256>>>(in_proj_w + (size_t)l * 3 * EE, w_h, w_l, 3 * EE / 4);
        split_h<<<1024, 256>>>(out_w + (size_t)l * EE, wo_h, wo_l, EE / 4);

        // q = (x @ Wq^T) * SCALE      (hi only)
        launch_gemm(false, x, 0, w_h, w_l, 0,
                    nullptr, q, nullptr, 0,
                    MTOT, EDIM, EDIM, EDIM, SCALE_Q, nullptr, 1);
        // k = target @ Wk^T           (hi+lo)
        launch_gemm(false, T, 0, w_h + EE, w_l + EE, 0,
                    nullptr, k_h, k_l, 0,
                    MTOT, EDIM, EDIM, EDIM, 1.f, nullptr, 1);
        // vT[b] = (target_b @ Wv^T)^T (hi+lo, transposed store)
        launch_gemm(true, T, (size_t)SKV * EDIM, w_h + 2 * EE, w_l + 2 * EE, 0,
                    nullptr, vT_h, vT_l, (size_t)EDIM * SKV,
                    SKV, EDIM, EDIM, SKV, 1.f, nullptr, NB);
        // scores[b] = q_b @ k_b^T     (fp32)
        launch_gemm(false, q, (size_t)SQ * EDIM, k_h, k_l, (size_t)SKV * EDIM,
                    sc, nullptr, nullptr, (size_t)SQ * SKV,
                    SQ, SKV, EDIM, SKV, 1.f, nullptr, NB);
        softmax_h<<<NB * SQ, 256>>>(sc, p);
        // o[b] = attn_b @ vT_b^T      (hi only)
        launch_gemm(false, p, (size_t)SQ * SKV, vT_h, vT_l, (size_t)EDIM * SKV,
                    nullptr, o, nullptr, (size_t)SQ * EDIM,
                    SQ, EDIM, SKV, EDIM, 1.f, nullptr, NB);
        // x = o @ out_w^T + out_b     (hi only)
        launch_gemm(false, o, 0, wo_h, wo_l, 0,
                    nullptr, x, nullptr, 0,
                    MTOT, EDIM, EDIM, EDIM, 1.f, out_b + (size_t)l * EDIM, 1);
    }

    // logits = x @ lin_w^T + lin_b    (fp32 out)
    split_h<<<4096, 256>>>(lin_w, lin_h, lin_l, (size_t)VOC * EDIM / 4);
    launch_gemm(false, x, 0, lin_h, lin_l, 0,
                logits, nullptr, nullptr, 0,
                MTOT, VOC, EDIM, VOC, 1.f, lin_b, 1);
}